// round 5
// baseline (speedup 1.0000x reference)
#include <cuda_runtime.h>
#include <cstdint>

#define NN 10000
#define EE 400000
#define HH 128
#define TPAD 132
#define APAD 36
#define NBLK 157   // ceil(NN/64)

typedef unsigned long long u64;

// ---------------- device scratch ----------------
__device__ float g_h  [NN * HH];
__device__ float g_agg[NN * HH];
__device__ float g_P  [NN * HH];
__device__ float g_Q  [NN * HH];
__device__ float g_inv [NN];
__device__ float g_flag[NN];
__device__ int   g_cnt[NN];
__device__ int   g_off[NN];
__device__ int   g_cur[NN];
__device__ float4 g_rec[EE];
__device__ float g_Wc[4][HH * HH];
__device__ float g_bc[4][HH];

// ---------------- packed f32x2 helpers ----------------
__device__ __forceinline__ u64 pack2(float x, float y) {
    u64 r; asm("mov.b64 %0,{%1,%2};" : "=l"(r) : "f"(x), "f"(y)); return r;
}
__device__ __forceinline__ float2 unpack2(u64 v) {
    float2 r; asm("mov.b64 {%0,%1},%2;" : "=f"(r.x), "=f"(r.y) : "l"(v)); return r;
}
__device__ __forceinline__ void ffma2(u64 &c, u64 a, u64 b) {
    asm("fma.rn.f32x2 %0,%1,%2,%0;" : "+l"(c) : "l"(a), "l"(b));
}

// M=64 micro-kernel: thread computes 4 rows x 8 cols. A row-major stride lda,
// k window [kbase,kbase+32), B tile Bs[kk][j] stride 128.
__device__ __forceinline__ void mm4(const float* __restrict__ A, int lda,
                                    int arow0, int kbase,
                                    const float* __restrict__ Bs,
                                    int tx, u64 acc[4][4]) {
#pragma unroll
    for (int kq = 0; kq < 8; ++kq) {
        int k0 = kq * 4;
        u64 bb[4][4];
#pragma unroll
        for (int kk = 0; kk < 4; ++kk) {
            const float* br = &Bs[(k0 + kk) * 128 + tx * 8];
            float4 b0 = *(const float4*)br;
            float4 b1 = *(const float4*)(br + 4);
            bb[kk][0] = pack2(b0.x, b0.y); bb[kk][1] = pack2(b0.z, b0.w);
            bb[kk][2] = pack2(b1.x, b1.y); bb[kk][3] = pack2(b1.z, b1.w);
        }
#pragma unroll
        for (int i = 0; i < 4; ++i) {
            float4 av = *(const float4*)&A[(arow0 + i) * lda + kbase + k0];
            float af[4] = { av.x, av.y, av.z, av.w };
#pragma unroll
            for (int kk = 0; kk < 4; ++kk) {
                u64 aa = pack2(af[kk], af[kk]);
#pragma unroll
                for (int jp = 0; jp < 4; ++jp) ffma2(acc[i][jp], aa, bb[kk][jp]);
            }
        }
    }
}

// ---------------- sort pipeline ----------------
__global__ void k_zero_cnt() {
    int i = blockIdx.x * blockDim.x + threadIdx.x;
    if (i < NN) g_cnt[i] = 0;
}
__global__ void k_count(const int* __restrict__ ei) {
    int e = blockIdx.x * blockDim.x + threadIdx.x;
    if (e < EE) atomicAdd(&g_cnt[ei[EE + e]], 1);
}
__global__ void k_scan() {
    __shared__ int ssum[256];
    int tid = threadIdx.x;
    int base = tid * 40;
    int s = 0;
    for (int i = 0; i < 40; ++i) {
        int n = base + i;
        if (n < NN) s += g_cnt[n];
    }
    ssum[tid] = s;
    __syncthreads();
    for (int o = 1; o < 256; o <<= 1) {
        int u = (tid >= o) ? ssum[tid - o] : 0;
        int v = ssum[tid];
        __syncthreads();
        ssum[tid] = u + v;
        __syncthreads();
    }
    int run = (tid > 0) ? ssum[tid - 1] : 0;
    for (int i = 0; i < 40; ++i) {
        int n = base + i;
        if (n < NN) {
            int c = g_cnt[n];
            g_off[n] = run;
            g_cur[n] = run;
            g_inv[n]  = 1.0f / fmaxf((float)c, 1.0f);
            g_flag[n] = (c > 0) ? 1.0f : 0.0f;
            run += c;
        }
    }
}
__global__ void k_place(const int* __restrict__ ei, const float* __restrict__ ea) {
    int e = blockIdx.x * blockDim.x + threadIdx.x;
    if (e >= EE) return;
    int tgt = ei[EE + e], src = ei[e];
    int pos = atomicAdd(&g_cur[tgt], 1);
    float4 r;
    r.x = __int_as_float(src);
    r.y = ea[(size_t)e * 3];
    r.z = ea[(size_t)e * 3 + 1];
    r.w = ea[(size_t)e * 3 + 2];
    g_rec[pos] = r;
}

// ---------------- fusion precompute ----------------
__global__ void k_fusew(const float* __restrict__ msg_w2, const float* __restrict__ upd_w1) {
    int l = blockIdx.y, k = blockIdx.x, c = threadIdx.x;
    __shared__ float row[128];
    row[c] = msg_w2[(size_t)l * 16384 + k * 128 + c];
    __syncthreads();
    const float* Wb = upd_w1 + (size_t)l * 32768 + 128 * 128;
    float s = 0.f;
#pragma unroll 8
    for (int j = 0; j < 128; ++j) s += row[j] * Wb[j * 128 + c];
    g_Wc[l][k * 128 + c] = s;
}
__global__ void k_fuseb(const float* __restrict__ msg_b2, const float* __restrict__ upd_w1) {
    int l = blockIdx.x, c = threadIdx.x;
    __shared__ float row[128];
    row[c] = msg_b2[l * 128 + c];
    __syncthreads();
    const float* Wb = upd_w1 + (size_t)l * 32768 + 128 * 128;
    float s = 0.f;
#pragma unroll 8
    for (int j = 0; j < 128; ++j) s += row[j] * Wb[j * 128 + c];
    g_bc[l][c] = s;
}

// ---------------- fused encoder: h = relu(x@w1+b1)@w2 + b2 ----------------
// grid NBLK, 256 thr. smem: Ts[64*TPAD] + Bs[32*128] + sx[64*6] + sw1[6*128] + sb1[128]
#define SM_ENC ((64 * TPAD + 32 * 128 + 64 * 6 + 6 * 128 + 128) * 4)
__global__ __launch_bounds__(256) void k_enc(
    const float* __restrict__ x,
    const float* __restrict__ w1, const float* __restrict__ b1,
    const float* __restrict__ w2, const float* __restrict__ b2) {
    extern __shared__ float sm[];
    float* Ts  = sm;
    float* Bs  = Ts + 64 * TPAD;
    float* sx  = Bs + 32 * 128;
    float* sw1 = sx + 64 * 6;
    float* sb1 = sw1 + 6 * 128;
    int tid = threadIdx.x;
    int tx = tid & 15, ty = tid >> 4;
    int n0 = blockIdx.x * 64;

    if (tid < 128) sb1[tid] = b1[tid];
    for (int i = tid; i < 64 * 6; i += 256) {
        int n = n0 + i / 6;
        sx[i] = (n < NN) ? x[(size_t)n * 6 + (i % 6)] : 0.f;
    }
    for (int i = tid; i < 768; i += 256) sw1[i] = w1[i];
    __syncthreads();

    // stage1: t = relu(x@w1+b1) -> Ts
#pragma unroll
    for (int i = 0; i < 4; ++i) {
        int e = ty * 4 + i;
        const float* xr = &sx[e * 6];
#pragma unroll
        for (int q = 0; q < 8; ++q) {
            int j = tx * 8 + q;
            float s = sb1[j];
#pragma unroll
            for (int k = 0; k < 6; ++k) s += xr[k] * sw1[k * 128 + j];
            Ts[e * TPAD + j] = fmaxf(s, 0.f);
        }
    }

    // stage2: h = t@w2 + b2
    u64 acc[4][4];
#pragma unroll
    for (int i = 0; i < 4; ++i)
#pragma unroll
        for (int jp = 0; jp < 4; ++jp) acc[i][jp] = 0ull;
    for (int kt = 0; kt < 4; ++kt) {
        __syncthreads();
#pragma unroll
        for (int r = 0; r < 16; ++r) {
            int idx = r * 256 + tid;
            int kk = idx >> 7, j = idx & 127;
            Bs[kk * 128 + j] = w2[(size_t)(kt * 32 + kk) * 128 + j];
        }
        __syncthreads();
        mm4(Ts, TPAD, ty * 4, kt * 32, Bs, tx, acc);
    }
    float bj[8];
#pragma unroll
    for (int q = 0; q < 8; ++q) bj[q] = b2[tx * 8 + q];
#pragma unroll
    for (int i = 0; i < 4; ++i) {
        int n = n0 + ty * 4 + i;
        if (n < NN) {
#pragma unroll
            for (int jp = 0; jp < 4; ++jp) {
                float2 c = unpack2(acc[i][jp]);
                c.x += bj[2 * jp]; c.y += bj[2 * jp + 1];
                *(float2*)&g_h[(size_t)n * 128 + tx * 8 + 2 * jp] = c;
            }
        }
    }
}

// ---------------- P/Q: fused single kernel, grid (NBLK, 2) ----------------
#define SM_G ((64 * APAD + 32 * 128) * 4)
__global__ __launch_bounds__(256) void k_pq(const float* __restrict__ W1,
                                            const float* __restrict__ B1m) {
    extern __shared__ float sm[];
    float* As = sm;
    float* Bs = sm + 64 * APAD;
    int tid = threadIdx.x;
    int tx = tid & 15, ty = tid >> 4;
    int n0 = blockIdx.x * 64;
    int half = blockIdx.y;                 // 0 -> P (+bias), 1 -> Q
    const float* W = W1 + (size_t)half * 128 * 128;
    float* outp = half ? g_Q : g_P;

    u64 acc[4][4];
#pragma unroll
    for (int i = 0; i < 4; ++i)
#pragma unroll
        for (int jp = 0; jp < 4; ++jp) acc[i][jp] = 0ull;

    for (int kt = 0; kt < 4; ++kt) {
        int kb = kt * 32;
        __syncthreads();
#pragma unroll
        for (int r = 0; r < 2; ++r) {
            int idx = r * 256 + tid;           // 512 float4 slots
            int e = idx >> 3, c4 = idx & 7;
            int n = n0 + e;
            float4 v = make_float4(0.f, 0.f, 0.f, 0.f);
            if (n < NN) v = *(const float4*)&g_h[(size_t)n * 128 + kb + c4 * 4];
            *(float4*)&As[e * APAD + c4 * 4] = v;
        }
#pragma unroll
        for (int r = 0; r < 16; ++r) {
            int idx = r * 256 + tid;
            int kk = idx >> 7, j = idx & 127;
            Bs[kk * 128 + j] = W[(size_t)(kb + kk) * 128 + j];
        }
        __syncthreads();
        mm4(As, APAD, ty * 4, 0, Bs, tx, acc);
    }

    float bj[8];
#pragma unroll
    for (int q = 0; q < 8; ++q) bj[q] = half ? 0.f : B1m[tx * 8 + q];
#pragma unroll
    for (int i = 0; i < 4; ++i) {
        int n = n0 + ty * 4 + i;
        if (n < NN) {
#pragma unroll
            for (int jp = 0; jp < 4; ++jp) {
                float2 c = unpack2(acc[i][jp]);
                c.x += bj[2 * jp]; c.y += bj[2 * jp + 1];
                *(float2*)&outp[(size_t)n * 128 + tx * 8 + 2 * jp] = c;
            }
        }
    }
}

// ---------------- segmented edge reduction ----------------
__global__ void k_edge_seg(const float* __restrict__ W1) {
    int wid = threadIdx.x >> 5, lane = threadIdx.x & 31;
    int n = blockIdx.x * 8 + wid;
    if (n >= NN) return;
    int c4 = lane * 4;
    float4 P4  = *(const float4*)&g_P[(size_t)n * 128 + c4];
    float4 wc0 = *(const float4*)&W1[(size_t)256 * 128 + c4];
    float4 wc1 = *(const float4*)&W1[(size_t)257 * 128 + c4];
    float4 wc2 = *(const float4*)&W1[(size_t)258 * 128 + c4];
    int start = g_off[n], deg = g_cnt[n];
    float4 acc = make_float4(0.f, 0.f, 0.f, 0.f);
    float4 rec = (deg > 0) ? g_rec[start] : make_float4(0.f, 0.f, 0.f, 0.f);
    for (int i = 0; i < deg; ++i) {
        float4 nrec = (i + 1 < deg) ? g_rec[start + i + 1] : rec;
        int src = __float_as_int(rec.x);
        float4 q = *(const float4*)&g_Q[(size_t)src * 128 + c4];
        float vx = P4.x + q.x + rec.y * wc0.x + rec.z * wc1.x + rec.w * wc2.x;
        float vy = P4.y + q.y + rec.y * wc0.y + rec.z * wc1.y + rec.w * wc2.y;
        float vz = P4.z + q.z + rec.y * wc0.z + rec.z * wc1.z + rec.w * wc2.z;
        float vw = P4.w + q.w + rec.y * wc0.w + rec.z * wc1.w + rec.w * wc2.w;
        acc.x += fmaxf(vx, 0.f);
        acc.y += fmaxf(vy, 0.f);
        acc.z += fmaxf(vz, 0.f);
        acc.w += fmaxf(vw, 0.f);
        rec = nrec;
    }
    float iv = g_inv[n];
    *(float4*)&g_agg[(size_t)n * 128 + c4] =
        make_float4(acc.x * iv, acc.y * iv, acc.z * iv, acc.w * iv);
}

// ---------------- update MLP (fused) + residual + layernorm, M=64 ----------------
#define SM_UPD ((64 * APAD + 32 * 128 + 64 * TPAD) * 4)
__global__ __launch_bounds__(256) void k_update(
    const float* __restrict__ W1top, const float* __restrict__ B1,
    int layer,
    const float* __restrict__ W2, const float* __restrict__ B2,
    const float* __restrict__ lng, const float* __restrict__ lnb) {
    extern __shared__ float sm[];
    float* As = sm;
    float* Bs = sm + 64 * APAD;
    float* Ts = Bs + 32 * 128;
    __shared__ float s_flag[64];
    __shared__ float s_bc[128];

    int tid = threadIdx.x;
    int tx = tid & 15, ty = tid >> 4;
    int n0 = blockIdx.x * 64;
    const float* __restrict__ Wc = g_Wc[layer];

    if (tid < 64) {
        int n = n0 + tid;
        s_flag[tid] = (n < NN) ? g_flag[n] : 0.f;
    }
    if (tid >= 128 && tid < 256) s_bc[tid - 128] = g_bc[layer][tid - 128];

    u64 acc[4][4];
#pragma unroll
    for (int i = 0; i < 4; ++i)
#pragma unroll
        for (int jp = 0; jp < 4; ++jp) acc[i][jp] = 0ull;

    // GEMM1: K=256 : h@Wa + Rmean@Wc
    for (int kt = 0; kt < 8; ++kt) {
        int kb = kt * 32;
        __syncthreads();
#pragma unroll
        for (int r = 0; r < 2; ++r) {
            int idx = r * 256 + tid;
            int e = idx >> 3, c4 = idx & 7;
            int n = n0 + e;
            float4 v = make_float4(0.f, 0.f, 0.f, 0.f);
            if (n < NN) {
                if (kb < 128) v = *(const float4*)&g_h[(size_t)n * 128 + kb + c4 * 4];
                else          v = *(const float4*)&g_agg[(size_t)n * 128 + (kb - 128) + c4 * 4];
            }
            *(float4*)&As[e * APAD + c4 * 4] = v;
        }
#pragma unroll
        for (int r = 0; r < 16; ++r) {
            int idx = r * 256 + tid;
            int kk = idx >> 7, j = idx & 127;
            float w;
            if (kb < 128) w = W1top[(size_t)(kb + kk) * 128 + j];
            else          w = Wc[(size_t)(kb - 128 + kk) * 128 + j];
            Bs[kk * 128 + j] = w;
        }
        __syncthreads();
        mm4(As, APAD, ty * 4, 0, Bs, tx, acc);
    }

    // epilogue1: relu(+b1u + flag*bc) -> Ts
    {
        float bj[8], bc[8];
#pragma unroll
        for (int q = 0; q < 8; ++q) { bj[q] = B1[tx * 8 + q]; bc[q] = s_bc[tx * 8 + q]; }
        __syncthreads();
#pragma unroll
        for (int i = 0; i < 4; ++i) {
            int e = ty * 4 + i;
            float fz = s_flag[e];
#pragma unroll
            for (int jp = 0; jp < 4; ++jp) {
                float2 c = unpack2(acc[i][jp]);
                c.x = fmaxf(c.x + bj[2 * jp]     + fz * bc[2 * jp],     0.f);
                c.y = fmaxf(c.y + bj[2 * jp + 1] + fz * bc[2 * jp + 1], 0.f);
                *(float2*)&Ts[e * TPAD + tx * 8 + 2 * jp] = c;
            }
        }
        __syncthreads();
    }

    // GEMM2: K=128
    u64 acc2[4][4];
#pragma unroll
    for (int i = 0; i < 4; ++i)
#pragma unroll
        for (int jp = 0; jp < 4; ++jp) acc2[i][jp] = 0ull;
    for (int kt = 0; kt < 4; ++kt) {
        __syncthreads();
#pragma unroll
        for (int r = 0; r < 16; ++r) {
            int idx = r * 256 + tid;
            int kk = idx >> 7, j = idx & 127;
            Bs[kk * 128 + j] = W2[(size_t)(kt * 32 + kk) * 128 + j];
        }
        __syncthreads();
        mm4(Ts, TPAD, ty * 4, kt * 32, Bs, tx, acc2);
    }

    // epilogue2: r = u + b2 + h -> Ts
    {
        float bj[8];
#pragma unroll
        for (int q = 0; q < 8; ++q) bj[q] = B2[tx * 8 + q];
        __syncthreads();
#pragma unroll
        for (int i = 0; i < 4; ++i) {
            int e = ty * 4 + i;
            int n = n0 + e;
#pragma unroll
            for (int jp = 0; jp < 4; ++jp) {
                float2 c = unpack2(acc2[i][jp]);
                float h0 = 0.f, h1 = 0.f;
                if (n < NN) {
                    float2 hv = *(const float2*)&g_h[(size_t)n * 128 + tx * 8 + 2 * jp];
                    h0 = hv.x; h1 = hv.y;
                }
                c.x += bj[2 * jp] + h0;
                c.y += bj[2 * jp + 1] + h1;
                *(float2*)&Ts[e * TPAD + tx * 8 + 2 * jp] = c;
            }
        }
        __syncthreads();
    }

    // layernorm: 8 warps x 8 rows -> g_h
    {
        int wid = tid >> 5, lane = tid & 31;
        for (int rr = 0; rr < 8; ++rr) {
            int e = wid * 8 + rr;
            int n = n0 + e;
            float v0 = Ts[e * TPAD + lane];
            float v1 = Ts[e * TPAD + lane + 32];
            float v2 = Ts[e * TPAD + lane + 64];
            float v3 = Ts[e * TPAD + lane + 96];
            float s = v0 + v1 + v2 + v3;
#pragma unroll
            for (int o = 16; o > 0; o >>= 1) s += __shfl_xor_sync(0xffffffffu, s, o);
            float mu = s * (1.0f / 128.0f);
            float d0 = v0 - mu, d1 = v1 - mu, d2 = v2 - mu, d3 = v3 - mu;
            float q = d0 * d0 + d1 * d1 + d2 * d2 + d3 * d3;
#pragma unroll
            for (int o = 16; o > 0; o >>= 1) q += __shfl_xor_sync(0xffffffffu, q, o);
            float rs = rsqrtf(q * (1.0f / 128.0f) + 1e-5f);
            if (n < NN) {
                size_t base = (size_t)n * 128;
                g_h[base + lane]      = d0 * rs * lng[lane]      + lnb[lane];
                g_h[base + lane + 32] = d1 * rs * lng[lane + 32] + lnb[lane + 32];
                g_h[base + lane + 64] = d2 * rs * lng[lane + 64] + lnb[lane + 64];
                g_h[base + lane + 96] = d3 * rs * lng[lane + 96] + lnb[lane + 96];
            }
        }
    }
}

// ---------------- fused decoder: out = relu(h@w1+b1).w2 + b2 ----------------
#define SM_DEC ((64 * TPAD + 32 * 128 + 64 * APAD + 128) * 4)
__global__ __launch_bounds__(256) void k_dec(
    const float* __restrict__ w1, const float* __restrict__ b1,
    const float* __restrict__ w2, const float* __restrict__ b2,
    float* __restrict__ out) {
    extern __shared__ float sm[];
    float* Ts  = sm;
    float* Bs  = Ts + 64 * TPAD;
    float* As  = Bs + 32 * 128;
    float* sw2 = As + 64 * APAD;
    int tid = threadIdx.x;
    int tx = tid & 15, ty = tid >> 4;
    int n0 = blockIdx.x * 64;

    if (tid < 128) sw2[tid] = w2[tid];

    u64 acc[4][4];
#pragma unroll
    for (int i = 0; i < 4; ++i)
#pragma unroll
        for (int jp = 0; jp < 4; ++jp) acc[i][jp] = 0ull;

    for (int kt = 0; kt < 4; ++kt) {
        int kb = kt * 32;
        __syncthreads();
#pragma unroll
        for (int r = 0; r < 2; ++r) {
            int idx = r * 256 + tid;
            int e = idx >> 3, c4 = idx & 7;
            int n = n0 + e;
            float4 v = make_float4(0.f, 0.f, 0.f, 0.f);
            if (n < NN) v = *(const float4*)&g_h[(size_t)n * 128 + kb + c4 * 4];
            *(float4*)&As[e * APAD + c4 * 4] = v;
        }
#pragma unroll
        for (int r = 0; r < 16; ++r) {
            int idx = r * 256 + tid;
            int kk = idx >> 7, j = idx & 127;
            Bs[kk * 128 + j] = w1[(size_t)(kb + kk) * 128 + j];
        }
        __syncthreads();
        mm4(As, APAD, ty * 4, 0, Bs, tx, acc);
    }

    float bj[8];
#pragma unroll
    for (int q = 0; q < 8; ++q) bj[q] = b1[tx * 8 + q];
#pragma unroll
    for (int i = 0; i < 4; ++i) {
        int e = ty * 4 + i;
#pragma unroll
        for (int jp = 0; jp < 4; ++jp) {
            float2 c = unpack2(acc[i][jp]);
            c.x = fmaxf(c.x + bj[2 * jp], 0.f);
            c.y = fmaxf(c.y + bj[2 * jp + 1], 0.f);
            *(float2*)&Ts[e * TPAD + tx * 8 + 2 * jp] = c;
        }
    }
    __syncthreads();

    // dot: 8 warps x 8 rows
    int wid = tid >> 5, lane = tid & 31;
    for (int rr = 0; rr < 8; ++rr) {
        int e = wid * 8 + rr;
        int n = n0 + e;
        float4 t = *(const float4*)&Ts[e * TPAD + lane * 4];
        float4 w = *(const float4*)&sw2[lane * 4];
        float s = t.x * w.x + t.y * w.y + t.z * w.z + t.w * w.w;
#pragma unroll
        for (int o = 16; o > 0; o >>= 1) s += __shfl_xor_sync(0xffffffffu, s, o);
        if (lane == 0 && n < NN) out[n] = s + b2[0];
    }
}

// ---------------- launch ----------------
extern "C" void kernel_launch(void* const* d_in, const int* in_sizes, int n_in,
                              void* d_out, int out_size) {
    const float* x      = (const float*)d_in[0];
    const int*   ei     = (const int*)  d_in[1];
    const float* eattr  = (const float*)d_in[2];
    const float* enc_w1 = (const float*)d_in[3];
    const float* enc_b1 = (const float*)d_in[4];
    const float* enc_w2 = (const float*)d_in[5];
    const float* enc_b2 = (const float*)d_in[6];
    const float* msg_w1 = (const float*)d_in[7];
    const float* msg_b1 = (const float*)d_in[8];
    const float* msg_w2 = (const float*)d_in[9];
    const float* msg_b2 = (const float*)d_in[10];
    const float* upd_w1 = (const float*)d_in[11];
    const float* upd_b1 = (const float*)d_in[12];
    const float* upd_w2 = (const float*)d_in[13];
    const float* upd_b2 = (const float*)d_in[14];
    const float* ln_g   = (const float*)d_in[15];
    const float* ln_b   = (const float*)d_in[16];
    const float* dec_w1 = (const float*)d_in[17];
    const float* dec_b1 = (const float*)d_in[18];
    const float* dec_w2 = (const float*)d_in[19];
    const float* dec_b2 = (const float*)d_in[20];
    float* out = (float*)d_out;

    cudaFuncSetAttribute(k_enc,    cudaFuncAttributeMaxDynamicSharedMemorySize, SM_ENC);
    cudaFuncSetAttribute(k_pq,     cudaFuncAttributeMaxDynamicSharedMemorySize, SM_G);
    cudaFuncSetAttribute(k_update, cudaFuncAttributeMaxDynamicSharedMemorySize, SM_UPD);
    cudaFuncSetAttribute(k_dec,    cudaFuncAttributeMaxDynamicSharedMemorySize, SM_DEC);

    // counting sort by target + degree stats
    k_zero_cnt<<<(NN + 255) / 256, 256>>>();
    k_count<<<(EE + 255) / 256, 256>>>(ei);
    k_scan<<<1, 256>>>();
    k_place<<<(EE + 255) / 256, 256>>>(ei, eattr);

    // fusion precompute
    k_fusew<<<dim3(128, 4), 128>>>(msg_w2, upd_w1);
    k_fuseb<<<4, 128>>>(msg_b2, upd_w1);

    // encoder
    k_enc<<<NBLK, 256, SM_ENC>>>(x, enc_w1, enc_b1, enc_w2, enc_b2);

    for (int l = 0; l < 4; ++l) {
        const float* W1l = msg_w1 + (size_t)l * 259 * 128;
        k_pq<<<dim3(NBLK, 2), 256, SM_G>>>(W1l, msg_b1 + (size_t)l * 128);
        k_edge_seg<<<NN / 8, 256>>>(W1l);
        k_update<<<NBLK, 256, SM_UPD>>>(
            upd_w1 + (size_t)l * 256 * 128, upd_b1 + (size_t)l * 128, l,
            upd_w2 + (size_t)l * 128 * 128, upd_b2 + (size_t)l * 128,
            ln_g + (size_t)l * 128, ln_b + (size_t)l * 128);
    }

    k_dec<<<NBLK, 256, SM_DEC>>>(dec_w1, dec_b1, dec_w2, dec_b2, out);
}

// round 6
// speedup vs baseline: 1.7186x; 1.7186x over previous
#include <cuda_runtime.h>
#include <cstdint>

#define NN 10000
#define EE 400000
#define HH 128
#define TPAD 132
#define APAD 36
#define NB128 79   // ceil(NN/128)

typedef unsigned long long u64;

// ---------------- device scratch ----------------
__device__ float g_h  [NN * HH];
__device__ float g_agg[NN * HH];
__device__ float g_P  [NN * HH];
__device__ float g_Q  [NN * HH];
__device__ float g_inv [NN];
__device__ float g_flag[NN];
__device__ int   g_cnt[NN];
__device__ int   g_off[NN];
__device__ int   g_cur[NN];
__device__ float4 g_rec[EE];
__device__ float g_Wc[4][HH * HH];
__device__ float g_bc[4][HH];

// ---------------- packed f32x2 helpers ----------------
__device__ __forceinline__ u64 pack2(float x, float y) {
    u64 r; asm("mov.b64 %0,{%1,%2};" : "=l"(r) : "f"(x), "f"(y)); return r;
}
__device__ __forceinline__ float2 unpack2(u64 v) {
    float2 r; asm("mov.b64 {%0,%1},%2;" : "=f"(r.x), "=f"(r.y) : "l"(v)); return r;
}
__device__ __forceinline__ void ffma2(u64 &c, u64 a, u64 b) {
    asm("fma.rn.f32x2 %0,%1,%2,%0;" : "+l"(c) : "l"(a), "l"(b));
}

// M=128 micro-kernel: thread computes 8 rows x 8 cols (proven round-4 config)
__device__ __forceinline__ void mm_row(const float* __restrict__ A, int lda,
                                       int arow0, int kbase,
                                       const float* __restrict__ Bs,
                                       int tx, u64 acc[8][4]) {
#pragma unroll
    for (int kq = 0; kq < 8; ++kq) {
        int k0 = kq * 4;
        u64 bb[4][4];
#pragma unroll
        for (int kk = 0; kk < 4; ++kk) {
            const float* br = &Bs[(k0 + kk) * 128 + tx * 8];
            float4 b0 = *(const float4*)br;
            float4 b1 = *(const float4*)(br + 4);
            bb[kk][0] = pack2(b0.x, b0.y); bb[kk][1] = pack2(b0.z, b0.w);
            bb[kk][2] = pack2(b1.x, b1.y); bb[kk][3] = pack2(b1.z, b1.w);
        }
#pragma unroll
        for (int i = 0; i < 8; ++i) {
            float4 av = *(const float4*)&A[(arow0 + i) * lda + kbase + k0];
            float af[4] = { av.x, av.y, av.z, av.w };
#pragma unroll
            for (int kk = 0; kk < 4; ++kk) {
                u64 aa = pack2(af[kk], af[kk]);
#pragma unroll
                for (int jp = 0; jp < 4; ++jp) ffma2(acc[i][jp], aa, bb[kk][jp]);
            }
        }
    }
}

// ---------------- sort pipeline ----------------
__global__ void k_zero_cnt() {
    int i = blockIdx.x * blockDim.x + threadIdx.x;
    if (i < NN) g_cnt[i] = 0;
}
__global__ void k_count(const int* __restrict__ ei) {
    int e = blockIdx.x * blockDim.x + threadIdx.x;
    if (e < EE) atomicAdd(&g_cnt[ei[EE + e]], 1);
}
__global__ void k_scan() {
    __shared__ int ssum[256];
    int tid = threadIdx.x;
    int base = tid * 40;
    int s = 0;
    for (int i = 0; i < 40; ++i) {
        int n = base + i;
        if (n < NN) s += g_cnt[n];
    }
    ssum[tid] = s;
    __syncthreads();
    for (int o = 1; o < 256; o <<= 1) {
        int u = (tid >= o) ? ssum[tid - o] : 0;
        int v = ssum[tid];
        __syncthreads();
        ssum[tid] = u + v;
        __syncthreads();
    }
    int run = (tid > 0) ? ssum[tid - 1] : 0;
    for (int i = 0; i < 40; ++i) {
        int n = base + i;
        if (n < NN) {
            int c = g_cnt[n];
            g_off[n] = run;
            g_cur[n] = run;
            g_inv[n]  = 1.0f / fmaxf((float)c, 1.0f);
            g_flag[n] = (c > 0) ? 1.0f : 0.0f;
            run += c;
        }
    }
}
__global__ void k_place(const int* __restrict__ ei, const float* __restrict__ ea) {
    int e = blockIdx.x * blockDim.x + threadIdx.x;
    if (e >= EE) return;
    int tgt = ei[EE + e], src = ei[e];
    int pos = atomicAdd(&g_cur[tgt], 1);
    float4 r;
    r.x = __int_as_float(src);
    r.y = ea[(size_t)e * 3];
    r.z = ea[(size_t)e * 3 + 1];
    r.w = ea[(size_t)e * 3 + 2];
    g_rec[pos] = r;
}

// ---------------- fusion precompute: Wc = W2m@Wb rows (k<128) and bc = b2m@Wb (k==128) ----------------
__global__ void k_fuse(const float* __restrict__ msg_w2, const float* __restrict__ msg_b2,
                       const float* __restrict__ upd_w1) {
    int l = blockIdx.y, k = blockIdx.x, c = threadIdx.x;
    __shared__ float row[128];
    row[c] = (k < 128) ? msg_w2[(size_t)l * 16384 + k * 128 + c] : msg_b2[l * 128 + c];
    __syncthreads();
    const float* Wb = upd_w1 + (size_t)l * 32768 + 128 * 128;
    float s = 0.f;
#pragma unroll 8
    for (int j = 0; j < 128; ++j) s += row[j] * Wb[j * 128 + c];
    if (k < 128) g_Wc[l][k * 128 + c] = s;
    else         g_bc[l][c] = s;
}

// ---------------- fused encoder: h = relu(x@w1+b1)@w2 + b2, M=128 ----------------
#define SM_ENC ((128 * TPAD + 32 * 128 + 128 * 6 + 6 * 128 + 128) * 4)
__global__ __launch_bounds__(256, 2) void k_enc(
    const float* __restrict__ x,
    const float* __restrict__ w1, const float* __restrict__ b1,
    const float* __restrict__ w2, const float* __restrict__ b2) {
    extern __shared__ float sm[];
    float* Ts  = sm;
    float* Bs  = Ts + 128 * TPAD;
    float* sx  = Bs + 32 * 128;
    float* sw1 = sx + 128 * 6;
    float* sb1 = sw1 + 6 * 128;
    int tid = threadIdx.x;
    int tx = tid & 15, ty = tid >> 4;
    int n0 = blockIdx.x * 128;

    if (tid < 128) sb1[tid] = b1[tid];
    for (int i = tid; i < 128 * 6; i += 256) {
        int n = n0 + i / 6;
        sx[i] = (n < NN) ? x[(size_t)n * 6 + (i % 6)] : 0.f;
    }
    for (int i = tid; i < 768; i += 256) sw1[i] = w1[i];
    __syncthreads();

    // stage1: t = relu(x@w1+b1) -> Ts
#pragma unroll
    for (int i = 0; i < 8; ++i) {
        int e = ty * 8 + i;
        const float* xr = &sx[e * 6];
#pragma unroll
        for (int q = 0; q < 8; ++q) {
            int j = tx * 8 + q;
            float s = sb1[j];
#pragma unroll
            for (int k = 0; k < 6; ++k) s += xr[k] * sw1[k * 128 + j];
            Ts[e * TPAD + j] = fmaxf(s, 0.f);
        }
    }

    // stage2: h = t@w2 + b2
    u64 acc[8][4];
#pragma unroll
    for (int i = 0; i < 8; ++i)
#pragma unroll
        for (int jp = 0; jp < 4; ++jp) acc[i][jp] = 0ull;
    for (int kt = 0; kt < 4; ++kt) {
        __syncthreads();
#pragma unroll
        for (int r = 0; r < 16; ++r) {
            int idx = r * 256 + tid;
            int kk = idx >> 7, j = idx & 127;
            Bs[kk * 128 + j] = w2[(size_t)(kt * 32 + kk) * 128 + j];
        }
        __syncthreads();
        mm_row(Ts, TPAD, ty * 8, kt * 32, Bs, tx, acc);
    }
    float bj[8];
#pragma unroll
    for (int q = 0; q < 8; ++q) bj[q] = b2[tx * 8 + q];
#pragma unroll
    for (int i = 0; i < 8; ++i) {
        int n = n0 + ty * 8 + i;
        if (n < NN) {
#pragma unroll
            for (int jp = 0; jp < 4; ++jp) {
                float2 c = unpack2(acc[i][jp]);
                c.x += bj[2 * jp]; c.y += bj[2 * jp + 1];
                *(float2*)&g_h[(size_t)n * 128 + tx * 8 + 2 * jp] = c;
            }
        }
    }
}

// ---------------- P/Q: one launch, grid (NB128, 2), M=128 ----------------
#define SM_G ((128 * APAD + 32 * 128) * 4)
__global__ __launch_bounds__(256, 2) void k_pq(const float* __restrict__ W1,
                                               const float* __restrict__ B1m) {
    extern __shared__ float sm[];
    float* As = sm;
    float* Bs = sm + 128 * APAD;
    int tid = threadIdx.x;
    int tx = tid & 15, ty = tid >> 4;
    int n0 = blockIdx.x * 128;
    int half = blockIdx.y;                  // 0 -> P (+bias), 1 -> Q
    const float* W = W1 + (size_t)half * 128 * 128;
    float* outp = half ? g_Q : g_P;

    u64 acc[8][4];
#pragma unroll
    for (int i = 0; i < 8; ++i)
#pragma unroll
        for (int jp = 0; jp < 4; ++jp) acc[i][jp] = 0ull;

    for (int kt = 0; kt < 4; ++kt) {
        int kb = kt * 32;
        __syncthreads();
#pragma unroll
        for (int r = 0; r < 4; ++r) {
            int idx = r * 256 + tid;
            int e = idx >> 3, c4 = idx & 7;
            int n = n0 + e;
            float4 v = make_float4(0.f, 0.f, 0.f, 0.f);
            if (n < NN) v = *(const float4*)&g_h[(size_t)n * 128 + kb + c4 * 4];
            *(float4*)&As[e * APAD + c4 * 4] = v;
        }
#pragma unroll
        for (int r = 0; r < 16; ++r) {
            int idx = r * 256 + tid;
            int kk = idx >> 7, j = idx & 127;
            Bs[kk * 128 + j] = W[(size_t)(kb + kk) * 128 + j];
        }
        __syncthreads();
        mm_row(As, APAD, ty * 8, 0, Bs, tx, acc);
    }

    float bj[8];
#pragma unroll
    for (int q = 0; q < 8; ++q) bj[q] = half ? 0.f : B1m[tx * 8 + q];
#pragma unroll
    for (int i = 0; i < 8; ++i) {
        int n = n0 + ty * 8 + i;
        if (n < NN) {
#pragma unroll
            for (int jp = 0; jp < 4; ++jp) {
                float2 c = unpack2(acc[i][jp]);
                c.x += bj[2 * jp]; c.y += bj[2 * jp + 1];
                *(float2*)&outp[(size_t)n * 128 + tx * 8 + 2 * jp] = c;
            }
        }
    }
}

// ---------------- segmented edge reduction ----------------
__global__ void k_edge_seg(const float* __restrict__ W1) {
    int wid = threadIdx.x >> 5, lane = threadIdx.x & 31;
    int n = blockIdx.x * 8 + wid;
    if (n >= NN) return;
    int c4 = lane * 4;
    float4 P4  = *(const float4*)&g_P[(size_t)n * 128 + c4];
    float4 wc0 = *(const float4*)&W1[(size_t)256 * 128 + c4];
    float4 wc1 = *(const float4*)&W1[(size_t)257 * 128 + c4];
    float4 wc2 = *(const float4*)&W1[(size_t)258 * 128 + c4];
    int start = g_off[n], deg = g_cnt[n];
    float4 acc = make_float4(0.f, 0.f, 0.f, 0.f);
    float4 rec = (deg > 0) ? g_rec[start] : make_float4(0.f, 0.f, 0.f, 0.f);
    for (int i = 0; i < deg; ++i) {
        float4 nrec = (i + 1 < deg) ? g_rec[start + i + 1] : rec;
        int src = __float_as_int(rec.x);
        float4 q = *(const float4*)&g_Q[(size_t)src * 128 + c4];
        float vx = P4.x + q.x + rec.y * wc0.x + rec.z * wc1.x + rec.w * wc2.x;
        float vy = P4.y + q.y + rec.y * wc0.y + rec.z * wc1.y + rec.w * wc2.y;
        float vz = P4.z + q.z + rec.y * wc0.z + rec.z * wc1.z + rec.w * wc2.z;
        float vw = P4.w + q.w + rec.y * wc0.w + rec.z * wc1.w + rec.w * wc2.w;
        acc.x += fmaxf(vx, 0.f);
        acc.y += fmaxf(vy, 0.f);
        acc.z += fmaxf(vz, 0.f);
        acc.w += fmaxf(vw, 0.f);
        rec = nrec;
    }
    float iv = g_inv[n];
    *(float4*)&g_agg[(size_t)n * 128 + c4] =
        make_float4(acc.x * iv, acc.y * iv, acc.z * iv, acc.w * iv);
}

// ---------------- update MLP (fused agg-GEMM) + residual + LN, M=128, in-place g_h ----------------
#define SM_UPD ((128 * APAD + 32 * 128 + 128 * TPAD) * 4)
__global__ __launch_bounds__(256, 2) void k_update(
    const float* __restrict__ W1top, const float* __restrict__ B1,
    int layer,
    const float* __restrict__ W2, const float* __restrict__ B2,
    const float* __restrict__ lng, const float* __restrict__ lnb) {
    extern __shared__ float sm[];
    float* As = sm;
    float* Bs = sm + 128 * APAD;
    float* Ts = Bs + 32 * 128;
    __shared__ float s_flag[128];
    __shared__ float s_bc[128];

    int tid = threadIdx.x;
    int tx = tid & 15, ty = tid >> 4;
    int n0 = blockIdx.x * 128;
    const float* __restrict__ Wc = g_Wc[layer];

    if (tid < 128) {
        int n = n0 + tid;
        s_flag[tid] = (n < NN) ? g_flag[n] : 0.f;
        s_bc[tid] = g_bc[layer][tid];
    }

    u64 acc[8][4];
#pragma unroll
    for (int i = 0; i < 8; ++i)
#pragma unroll
        for (int jp = 0; jp < 4; ++jp) acc[i][jp] = 0ull;

    // GEMM1: K=256 : h@Wa + Rmean@Wc
    for (int kt = 0; kt < 8; ++kt) {
        int kb = kt * 32;
        __syncthreads();
#pragma unroll
        for (int r = 0; r < 4; ++r) {
            int idx = r * 256 + tid;
            int e = idx >> 3, c4 = idx & 7;
            int n = n0 + e;
            float4 v = make_float4(0.f, 0.f, 0.f, 0.f);
            if (n < NN) {
                if (kb < 128) v = *(const float4*)&g_h[(size_t)n * 128 + kb + c4 * 4];
                else          v = *(const float4*)&g_agg[(size_t)n * 128 + (kb - 128) + c4 * 4];
            }
            *(float4*)&As[e * APAD + c4 * 4] = v;
        }
#pragma unroll
        for (int r = 0; r < 16; ++r) {
            int idx = r * 256 + tid;
            int kk = idx >> 7, j = idx & 127;
            float w;
            if (kb < 128) w = W1top[(size_t)(kb + kk) * 128 + j];
            else          w = Wc[(size_t)(kb - 128 + kk) * 128 + j];
            Bs[kk * 128 + j] = w;
        }
        __syncthreads();
        mm_row(As, APAD, ty * 8, 0, Bs, tx, acc);
    }

    // epilogue1: relu(+b1u + flag*bc) -> Ts
    {
        float bj[8], bc[8];
#pragma unroll
        for (int q = 0; q < 8; ++q) { bj[q] = B1[tx * 8 + q]; bc[q] = s_bc[tx * 8 + q]; }
        __syncthreads();
#pragma unroll
        for (int i = 0; i < 8; ++i) {
            int e = ty * 8 + i;
            float fz = s_flag[e];
#pragma unroll
            for (int jp = 0; jp < 4; ++jp) {
                float2 c = unpack2(acc[i][jp]);
                c.x = fmaxf(c.x + bj[2 * jp]     + fz * bc[2 * jp],     0.f);
                c.y = fmaxf(c.y + bj[2 * jp + 1] + fz * bc[2 * jp + 1], 0.f);
                *(float2*)&Ts[e * TPAD + tx * 8 + 2 * jp] = c;
            }
        }
        __syncthreads();
    }

    // GEMM2: K=128
    u64 acc2[8][4];
#pragma unroll
    for (int i = 0; i < 8; ++i)
#pragma unroll
        for (int jp = 0; jp < 4; ++jp) acc2[i][jp] = 0ull;
    for (int kt = 0; kt < 4; ++kt) {
        __syncthreads();
#pragma unroll
        for (int r = 0; r < 16; ++r) {
            int idx = r * 256 + tid;
            int kk = idx >> 7, j = idx & 127;
            Bs[kk * 128 + j] = W2[(size_t)(kt * 32 + kk) * 128 + j];
        }
        __syncthreads();
        mm_row(Ts, TPAD, ty * 8, kt * 32, Bs, tx, acc2);
    }

    // epilogue2: r = u + b2 + h -> Ts
    {
        float bj[8];
#pragma unroll
        for (int q = 0; q < 8; ++q) bj[q] = B2[tx * 8 + q];
        __syncthreads();
#pragma unroll
        for (int i = 0; i < 8; ++i) {
            int e = ty * 8 + i;
            int n = n0 + e;
#pragma unroll
            for (int jp = 0; jp < 4; ++jp) {
                float2 c = unpack2(acc2[i][jp]);
                float h0 = 0.f, h1 = 0.f;
                if (n < NN) {
                    float2 hv = *(const float2*)&g_h[(size_t)n * 128 + tx * 8 + 2 * jp];
                    h0 = hv.x; h1 = hv.y;
                }
                c.x += bj[2 * jp] + h0;
                c.y += bj[2 * jp + 1] + h1;
                *(float2*)&Ts[e * TPAD + tx * 8 + 2 * jp] = c;
            }
        }
        __syncthreads();
    }

    // layernorm -> g_h (in place; block touches only its own rows)
    {
        int wid = tid >> 5, lane = tid & 31;
        for (int rr = 0; rr < 16; ++rr) {
            int e = wid * 16 + rr;
            int n = n0 + e;
            float v0 = Ts[e * TPAD + lane];
            float v1 = Ts[e * TPAD + lane + 32];
            float v2 = Ts[e * TPAD + lane + 64];
            float v3 = Ts[e * TPAD + lane + 96];
            float s = v0 + v1 + v2 + v3;
#pragma unroll
            for (int o = 16; o > 0; o >>= 1) s += __shfl_xor_sync(0xffffffffu, s, o);
            float mu = s * (1.0f / 128.0f);
            float d0 = v0 - mu, d1 = v1 - mu, d2 = v2 - mu, d3 = v3 - mu;
            float q = d0 * d0 + d1 * d1 + d2 * d2 + d3 * d3;
#pragma unroll
            for (int o = 16; o > 0; o >>= 1) q += __shfl_xor_sync(0xffffffffu, q, o);
            float rs = rsqrtf(q * (1.0f / 128.0f) + 1e-5f);
            if (n < NN) {
                size_t base = (size_t)n * 128;
                g_h[base + lane]      = d0 * rs * lng[lane]      + lnb[lane];
                g_h[base + lane + 32] = d1 * rs * lng[lane + 32] + lnb[lane + 32];
                g_h[base + lane + 64] = d2 * rs * lng[lane + 64] + lnb[lane + 64];
                g_h[base + lane + 96] = d3 * rs * lng[lane + 96] + lnb[lane + 96];
            }
        }
    }
}

// ---------------- fused decoder: out = relu(h@w1+b1).w2 + b2, M=128 ----------------
#define SM_DEC ((128 * APAD + 32 * 128 + 128 * TPAD + 128) * 4)
__global__ __launch_bounds__(256, 2) void k_dec(
    const float* __restrict__ w1, const float* __restrict__ b1,
    const float* __restrict__ w2, const float* __restrict__ b2,
    float* __restrict__ out) {
    extern __shared__ float sm[];
    float* As  = sm;
    float* Bs  = As + 128 * APAD;
    float* Ts  = Bs + 32 * 128;
    float* sw2 = Ts + 128 * TPAD;
    int tid = threadIdx.x;
    int tx = tid & 15, ty = tid >> 4;
    int n0 = blockIdx.x * 128;

    if (tid < 128) sw2[tid] = w2[tid];

    u64 acc[8][4];
#pragma unroll
    for (int i = 0; i < 8; ++i)
#pragma unroll
        for (int jp = 0; jp < 4; ++jp) acc[i][jp] = 0ull;

    for (int kt = 0; kt < 4; ++kt) {
        int kb = kt * 32;
        __syncthreads();
#pragma unroll
        for (int r = 0; r < 4; ++r) {
            int idx = r * 256 + tid;
            int e = idx >> 3, c4 = idx & 7;
            int n = n0 + e;
            float4 v = make_float4(0.f, 0.f, 0.f, 0.f);
            if (n < NN) v = *(const float4*)&g_h[(size_t)n * 128 + kb + c4 * 4];
            *(float4*)&As[e * APAD + c4 * 4] = v;
        }
#pragma unroll
        for (int r = 0; r < 16; ++r) {
            int idx = r * 256 + tid;
            int kk = idx >> 7, j = idx & 127;
            Bs[kk * 128 + j] = w1[(size_t)(kb + kk) * 128 + j];
        }
        __syncthreads();
        mm_row(As, APAD, ty * 8, 0, Bs, tx, acc);
    }

    float bj[8];
#pragma unroll
    for (int q = 0; q < 8; ++q) bj[q] = b1[tx * 8 + q];
#pragma unroll
    for (int i = 0; i < 8; ++i) {
        int e = ty * 8 + i;
#pragma unroll
        for (int jp = 0; jp < 4; ++jp) {
            float2 c = unpack2(acc[i][jp]);
            c.x = fmaxf(c.x + bj[2 * jp], 0.f);
            c.y = fmaxf(c.y + bj[2 * jp + 1], 0.f);
            *(float2*)&Ts[e * TPAD + tx * 8 + 2 * jp] = c;
        }
    }
    __syncthreads();

    // dot: 8 warps x 16 rows
    int wid = tid >> 5, lane = tid & 31;
    for (int rr = 0; rr < 16; ++rr) {
        int e = wid * 16 + rr;
        int n = n0 + e;
        float4 t = *(const float4*)&Ts[e * TPAD + lane * 4];
        float4 w = *(const float4*)&sw2[lane * 4];
        float s = t.x * w.x + t.y * w.y + t.z * w.z + t.w * w.w;
#pragma unroll
        for (int o = 16; o > 0; o >>= 1) s += __shfl_xor_sync(0xffffffffu, s, o);
        if (lane == 0 && n < NN) out[n] = s + b2[0];
    }
}

// ---------------- launch ----------------
extern "C" void kernel_launch(void* const* d_in, const int* in_sizes, int n_in,
                              void* d_out, int out_size) {
    const float* x      = (const float*)d_in[0];
    const int*   ei     = (const int*)  d_in[1];
    const float* eattr  = (const float*)d_in[2];
    const float* enc_w1 = (const float*)d_in[3];
    const float* enc_b1 = (const float*)d_in[4];
    const float* enc_w2 = (const float*)d_in[5];
    const float* enc_b2 = (const float*)d_in[6];
    const float* msg_w1 = (const float*)d_in[7];
    const float* msg_b1 = (const float*)d_in[8];
    const float* msg_w2 = (const float*)d_in[9];
    const float* msg_b2 = (const float*)d_in[10];
    const float* upd_w1 = (const float*)d_in[11];
    const float* upd_b1 = (const float*)d_in[12];
    const float* upd_w2 = (const float*)d_in[13];
    const float* upd_b2 = (const float*)d_in[14];
    const float* ln_g   = (const float*)d_in[15];
    const float* ln_b   = (const float*)d_in[16];
    const float* dec_w1 = (const float*)d_in[17];
    const float* dec_b1 = (const float*)d_in[18];
    const float* dec_w2 = (const float*)d_in[19];
    const float* dec_b2 = (const float*)d_in[20];
    float* out = (float*)d_out;

    cudaFuncSetAttribute(k_enc,    cudaFuncAttributeMaxDynamicSharedMemorySize, SM_ENC);
    cudaFuncSetAttribute(k_pq,     cudaFuncAttributeMaxDynamicSharedMemorySize, SM_G);
    cudaFuncSetAttribute(k_update, cudaFuncAttributeMaxDynamicSharedMemorySize, SM_UPD);
    cudaFuncSetAttribute(k_dec,    cudaFuncAttributeMaxDynamicSharedMemorySize, SM_DEC);

    // counting sort by target + degree stats
    k_zero_cnt<<<(NN + 255) / 256, 256>>>();
    k_count<<<(EE + 255) / 256, 256>>>(ei);
    k_scan<<<1, 256>>>();
    k_place<<<(EE + 255) / 256, 256>>>(ei, eattr);

    // fusion precompute (Wc rows + bc row in one kernel)
    k_fuse<<<dim3(129, 4), 128>>>(msg_w2, msg_b2, upd_w1);

    // encoder
    k_enc<<<NB128, 256, SM_ENC>>>(x, enc_w1, enc_b1, enc_w2, enc_b2);

    for (int l = 0; l < 4; ++l) {
        const float* W1l = msg_w1 + (size_t)l * 259 * 128;
        k_pq<<<dim3(NB128, 2), 256, SM_G>>>(W1l, msg_b1 + (size_t)l * 128);
        k_edge_seg<<<NN / 8, 256>>>(W1l);
        k_update<<<NB128, 256, SM_UPD>>>(
            upd_w1 + (size_t)l * 256 * 128, upd_b1 + (size_t)l * 128, l,
            upd_w2 + (size_t)l * 128 * 128, upd_b2 + (size_t)l * 128,
            ln_g + (size_t)l * 128, ln_b + (size_t)l * 128);
    }

    k_dec<<<NB128, 256, SM_DEC>>>(dec_w1, dec_b1, dec_w2, dec_b2, out);
}